// round 3
// baseline (speedup 1.0000x reference)
#include <cuda_runtime.h>
#include <cuda_bf16.h>
#include <math.h>

#define NLEV 16
#define TBL (1u << 19)

// floor(16 * 1.3819^l) computed in double precision
__device__ __constant__ int c_res[16] = {16, 22, 30, 42, 58, 80, 111, 153,
                                         212, 294, 406, 561, 775, 1072, 1481, 2047};

__global__ __launch_bounds__(128, 4)
void nerf_fused_kernel(const float* __restrict__ xyz,
                       const float* __restrict__ dirp,
                       const float* __restrict__ table,
                       const float* __restrict__ w1,
                       const float* __restrict__ w2,
                       const float* __restrict__ wr1,
                       const float* __restrict__ wr2,
                       const float* __restrict__ wr3,
                       float* __restrict__ out, int N)
{
    __shared__ __align__(16) float sW1[32 * 64];
    __shared__ __align__(16) float sW2[64 * 20];   // 64x17 padded to stride 20
    __shared__ __align__(16) float sR1[32 * 64];
    __shared__ __align__(16) float sR2[64 * 64];
    __shared__ __align__(16) float sR3[64 * 4];    // 64x3 padded to stride 4

    const int tid = threadIdx.x;
    for (int i = tid; i < 32 * 64; i += 128) sW1[i] = w1[i];
    for (int i = tid; i < 64 * 20; i += 128) {
        int r = i / 20, c = i % 20;
        sW2[i] = (c < 17) ? w2[r * 17 + c] : 0.0f;
    }
    for (int i = tid; i < 32 * 64; i += 128) sR1[i] = wr1[i];
    for (int i = tid; i < 64 * 64; i += 128) sR2[i] = wr2[i];
    for (int i = tid; i < 64 * 4; i += 128) {
        int r = i / 4, c = i % 4;
        sR3[i] = (c < 3) ? wr3[r * 3 + c] : 0.0f;
    }
    __syncthreads();

    const int idx = blockIdx.x * 128 + tid;
    if (idx >= N) return;

    const float x = xyz[3 * idx + 0];
    const float y = xyz[3 * idx + 1];
    const float z = xyz[3 * idx + 2];

    // ---------------- hash grid encode fused with sigma layer 1 ----------------
    // h[j] = sum_l (e_{2l} * W1[2l][j] + e_{2l+1} * W1[2l+1][j]), relu at the end
    float h[64];
    #pragma unroll
    for (int j = 0; j < 64; j++) h[j] = 0.0f;

    #pragma unroll
    for (int l = 0; l < NLEV; l++) {
        const int res = c_res[l];
        const float rf = (float)res;
        const float px = x * rf, py = y * rf, pz = z * rf;
        const float fx = floorf(px), fy = floorf(py), fz = floorf(pz);
        const float wx = px - fx, wy = py - fy, wz = pz - fz;
        const unsigned X = (unsigned)fx, Y = (unsigned)fy, Z = (unsigned)fz;

        unsigned id0, id1, id2, id3, id4, id5, id6, id7;
        if (l < 5) {   // dense levels
            const unsigned s  = (unsigned)(res + 1);
            const unsigned s2 = s * s;
            const unsigned base = X + Y * s + Z * s2;
            id0 = base;          id1 = base + 1u;
            id2 = base + s;      id3 = base + s + 1u;
            id4 = base + s2;     id5 = base + s2 + 1u;
            id6 = base + s2 + s; id7 = base + s2 + s + 1u;
        } else {       // hashed levels
            const unsigned P1 = 2654435761u, P2 = 805459861u;
            const unsigned hx0 = X, hx1 = X + 1u;
            const unsigned hy0 = Y * P1, hy1 = (Y + 1u) * P1;
            const unsigned hz0 = Z * P2, hz1 = (Z + 1u) * P2;
            const unsigned M = TBL - 1u;
            id0 = (hx0 ^ hy0 ^ hz0) & M;  id1 = (hx1 ^ hy0 ^ hz0) & M;
            id2 = (hx0 ^ hy1 ^ hz0) & M;  id3 = (hx1 ^ hy1 ^ hz0) & M;
            id4 = (hx0 ^ hy0 ^ hz1) & M;  id5 = (hx1 ^ hy0 ^ hz1) & M;
            id6 = (hx0 ^ hy1 ^ hz1) & M;  id7 = (hx1 ^ hy1 ^ hz1) & M;
        }

        const float2* tl = (const float2*)table + (size_t)l * TBL;
        const float2 f0 = __ldg(tl + id0);
        const float2 f1 = __ldg(tl + id1);
        const float2 f2 = __ldg(tl + id2);
        const float2 f3 = __ldg(tl + id3);
        const float2 f4 = __ldg(tl + id4);
        const float2 f5 = __ldg(tl + id5);
        const float2 f6 = __ldg(tl + id6);
        const float2 f7 = __ldg(tl + id7);

        const float wx0 = 1.0f - wx, wy0 = 1.0f - wy, wz0 = 1.0f - wz;
        const float w00 = wy0 * wz0, w10 = wy * wz0, w01 = wy0 * wz, w11 = wy * wz;
        const float c0 = wx0 * w00, c1 = wx * w00;
        const float c2 = wx0 * w10, c3 = wx * w10;
        const float c4 = wx0 * w01, c5 = wx * w01;
        const float c6 = wx0 * w11, c7 = wx * w11;

        float e0 = f0.x * c0; float e1 = f0.y * c0;
        e0 = fmaf(f1.x, c1, e0); e1 = fmaf(f1.y, c1, e1);
        e0 = fmaf(f2.x, c2, e0); e1 = fmaf(f2.y, c2, e1);
        e0 = fmaf(f3.x, c3, e0); e1 = fmaf(f3.y, c3, e1);
        e0 = fmaf(f4.x, c4, e0); e1 = fmaf(f4.y, c4, e1);
        e0 = fmaf(f5.x, c5, e0); e1 = fmaf(f5.y, c5, e1);
        e0 = fmaf(f6.x, c6, e0); e1 = fmaf(f6.y, c6, e1);
        e0 = fmaf(f7.x, c7, e0); e1 = fmaf(f7.y, c7, e1);

        const float* wa = sW1 + (2 * l) * 64;
        const float* wb = sW1 + (2 * l + 1) * 64;
        #pragma unroll
        for (int j = 0; j < 64; j += 4) {
            const float4 va = *(const float4*)(wa + j);
            const float4 vb = *(const float4*)(wb + j);
            h[j + 0] = fmaf(e0, va.x, fmaf(e1, vb.x, h[j + 0]));
            h[j + 1] = fmaf(e0, va.y, fmaf(e1, vb.y, h[j + 1]));
            h[j + 2] = fmaf(e0, va.z, fmaf(e1, vb.z, h[j + 2]));
            h[j + 3] = fmaf(e0, va.w, fmaf(e1, vb.w, h[j + 3]));
        }
    }
    #pragma unroll
    for (int j = 0; j < 64; j++) h[j] = fmaxf(h[j], 0.0f);

    // ---------------- sigma layer 2: 64 -> 17 ----------------
    float g[20];
    #pragma unroll
    for (int j = 0; j < 20; j += 4) {
        float a0 = 0.f, a1 = 0.f, a2 = 0.f, a3 = 0.f;
        #pragma unroll
        for (int i = 0; i < 64; i++) {
            const float4 wv = *(const float4*)(sW2 + i * 20 + j);
            a0 = fmaf(h[i], wv.x, a0);
            a1 = fmaf(h[i], wv.y, a1);
            a2 = fmaf(h[i], wv.z, a2);
            a3 = fmaf(h[i], wv.w, a3);
        }
        g[j + 0] = a0; g[j + 1] = a1; g[j + 2] = a2; g[j + 3] = a3;
    }
    const float sigma = g[0];   // g[1..16] = geo_feat

    // ---------------- SH encode of direction ----------------
    const float dx = dirp[3 * idx + 0] * 2.0f - 1.0f;
    const float dy = dirp[3 * idx + 1] * 2.0f - 1.0f;
    const float dz = dirp[3 * idx + 2] * 2.0f - 1.0f;
    const float x2 = dx * dx, y2 = dy * dy, z2 = dz * dz;
    const float xy = dx * dy, yz = dy * dz, xz = dx * dz;

    float rin[32];
    rin[0]  = 0.28209479177387814f;
    rin[1]  = -0.48860251190291987f * dy;
    rin[2]  = 0.48860251190291987f * dz;
    rin[3]  = -0.48860251190291987f * dx;
    rin[4]  = 1.0925484305920792f * xy;
    rin[5]  = -1.0925484305920792f * yz;
    rin[6]  = 0.94617469575756f * z2 - 0.31539156525252f;
    rin[7]  = -1.0925484305920792f * xz;
    rin[8]  = 0.5462742152960396f * (x2 - y2);
    rin[9]  = 0.5900435899266435f * dy * (-3.0f * x2 + y2);
    rin[10] = 2.890611442640554f * xy * dz;
    rin[11] = 0.4570457994644657f * dy * (1.0f - 5.0f * z2);
    rin[12] = 0.3731763325901154f * dz * (5.0f * z2 - 3.0f);
    rin[13] = 0.4570457994644657f * dx * (1.0f - 5.0f * z2);
    rin[14] = 1.445305721320277f * dz * (x2 - y2);
    rin[15] = 0.5900435899266435f * dx * (-x2 + 3.0f * y2);
    #pragma unroll
    for (int i = 0; i < 16; i++) rin[16 + i] = g[1 + i];

    // ---------------- rgb layer 1: 32 -> 64 (relu), reuse h ----------------
    #pragma unroll
    for (int j = 0; j < 64; j += 4) {
        float a0 = 0.f, a1 = 0.f, a2 = 0.f, a3 = 0.f;
        #pragma unroll
        for (int i = 0; i < 32; i++) {
            const float4 wv = *(const float4*)(sR1 + i * 64 + j);
            a0 = fmaf(rin[i], wv.x, a0);
            a1 = fmaf(rin[i], wv.y, a1);
            a2 = fmaf(rin[i], wv.z, a2);
            a3 = fmaf(rin[i], wv.w, a3);
        }
        h[j + 0] = fmaxf(a0, 0.f);
        h[j + 1] = fmaxf(a1, 0.f);
        h[j + 2] = fmaxf(a2, 0.f);
        h[j + 3] = fmaxf(a3, 0.f);
    }

    // ---------------- rgb layers 2+3 fused: 64 -> relu -> 3 ----------------
    // h2[j] is computed as a scalar and immediately folded into r0..r2.
    float r0 = 0.f, r1 = 0.f, r2 = 0.f;
    #pragma unroll
    for (int j = 0; j < 64; j += 2) {
        float a0 = 0.f, a1 = 0.f;
        #pragma unroll
        for (int i = 0; i < 64; i++) {
            const float2 wv = *(const float2*)(sR2 + i * 64 + j);
            a0 = fmaf(h[i], wv.x, a0);
            a1 = fmaf(h[i], wv.y, a1);
        }
        a0 = fmaxf(a0, 0.f);
        a1 = fmaxf(a1, 0.f);
        const float4 w3a = *(const float4*)(sR3 + (j + 0) * 4);
        const float4 w3b = *(const float4*)(sR3 + (j + 1) * 4);
        r0 = fmaf(a0, w3a.x, fmaf(a1, w3b.x, r0));
        r1 = fmaf(a0, w3a.y, fmaf(a1, w3b.y, r1));
        r2 = fmaf(a0, w3a.z, fmaf(a1, w3b.z, r2));
    }

    // ---------------- outputs: sigmoid(rgb) [N,3], relu(sigma) [N,1] ----------------
    out[3 * idx + 0] = 1.0f / (1.0f + __expf(-r0));
    out[3 * idx + 1] = 1.0f / (1.0f + __expf(-r1));
    out[3 * idx + 2] = 1.0f / (1.0f + __expf(-r2));
    out[(size_t)3 * N + idx] = fmaxf(sigma, 0.f);
}

extern "C" void kernel_launch(void* const* d_in, const int* in_sizes, int n_in,
                              void* d_out, int out_size)
{
    const float* xyz   = (const float*)d_in[0];
    const float* dirp  = (const float*)d_in[1];
    const float* table = (const float*)d_in[2];
    const float* w1    = (const float*)d_in[3];
    const float* w2    = (const float*)d_in[4];
    const float* wr1   = (const float*)d_in[5];
    const float* wr2   = (const float*)d_in[6];
    const float* wr3   = (const float*)d_in[7];
    float* out = (float*)d_out;

    const int N = in_sizes[0] / 3;
    const int grid = (N + 127) / 128;
    nerf_fused_kernel<<<grid, 128>>>(xyz, dirp, table, w1, w2, wr1, wr2, wr3, out, N);
}

// round 5
// speedup vs baseline: 1.3137x; 1.3137x over previous
#include <cuda_runtime.h>
#include <cuda_bf16.h>
#include <math.h>

#define NLEV 16
#define TBL (1u << 19)
#define NMAX (1u << 21)

// scratch: enc features, feature-major [32][N] for coalesced access both ways
__device__ float g_enc[32u * NMAX];

// floor(16 * 1.3819^l) computed in double precision
__device__ __constant__ int c_res[16] = {16, 22, 30, 42, 58, 80, 111, 153,
                                         212, 294, 406, 561, 775, 1072, 1481, 2047};

// ================= K1: hash-grid encode (gather-bound, high occupancy) =================
__global__ __launch_bounds__(256)
void encode_kernel(const float* __restrict__ xyz,
                   const float* __restrict__ table, int N)
{
    const int idx = blockIdx.x * 256 + threadIdx.x;
    if (idx >= N) return;

    const float x = xyz[3 * idx + 0];
    const float y = xyz[3 * idx + 1];
    const float z = xyz[3 * idx + 2];

    #pragma unroll
    for (int l = 0; l < NLEV; l++) {
        const int res = c_res[l];
        const float rf = (float)res;
        const float px = x * rf, py = y * rf, pz = z * rf;
        const float fx = floorf(px), fy = floorf(py), fz = floorf(pz);
        const float wx = px - fx, wy = py - fy, wz = pz - fz;
        const unsigned X = (unsigned)fx, Y = (unsigned)fy, Z = (unsigned)fz;

        unsigned id0, id1, id2, id3, id4, id5, id6, id7;
        if (l < 5) {   // dense levels
            const unsigned s  = (unsigned)(res + 1);
            const unsigned s2 = s * s;
            const unsigned base = X + Y * s + Z * s2;
            id0 = base;          id1 = base + 1u;
            id2 = base + s;      id3 = base + s + 1u;
            id4 = base + s2;     id5 = base + s2 + 1u;
            id6 = base + s2 + s; id7 = base + s2 + s + 1u;
        } else {       // hashed levels
            const unsigned P1 = 2654435761u, P2 = 805459861u;
            const unsigned hx0 = X, hx1 = X + 1u;
            const unsigned hy0 = Y * P1, hy1 = (Y + 1u) * P1;
            const unsigned hz0 = Z * P2, hz1 = (Z + 1u) * P2;
            const unsigned M = TBL - 1u;
            id0 = (hx0 ^ hy0 ^ hz0) & M;  id1 = (hx1 ^ hy0 ^ hz0) & M;
            id2 = (hx0 ^ hy1 ^ hz0) & M;  id3 = (hx1 ^ hy1 ^ hz0) & M;
            id4 = (hx0 ^ hy0 ^ hz1) & M;  id5 = (hx1 ^ hy0 ^ hz1) & M;
            id6 = (hx0 ^ hy1 ^ hz1) & M;  id7 = (hx1 ^ hy1 ^ hz1) & M;
        }

        const float2* tl = (const float2*)table + (size_t)l * TBL;
        const float2 f0 = __ldg(tl + id0);
        const float2 f1 = __ldg(tl + id1);
        const float2 f2 = __ldg(tl + id2);
        const float2 f3 = __ldg(tl + id3);
        const float2 f4 = __ldg(tl + id4);
        const float2 f5 = __ldg(tl + id5);
        const float2 f6 = __ldg(tl + id6);
        const float2 f7 = __ldg(tl + id7);

        const float wx0 = 1.0f - wx, wy0 = 1.0f - wy, wz0 = 1.0f - wz;
        const float w00 = wy0 * wz0, w10 = wy * wz0, w01 = wy0 * wz, w11 = wy * wz;
        const float c0 = wx0 * w00, c1 = wx * w00;
        const float c2 = wx0 * w10, c3 = wx * w10;
        const float c4 = wx0 * w01, c5 = wx * w01;
        const float c6 = wx0 * w11, c7 = wx * w11;

        float e0 = f0.x * c0; float e1 = f0.y * c0;
        e0 = fmaf(f1.x, c1, e0); e1 = fmaf(f1.y, c1, e1);
        e0 = fmaf(f2.x, c2, e0); e1 = fmaf(f2.y, c2, e1);
        e0 = fmaf(f3.x, c3, e0); e1 = fmaf(f3.y, c3, e1);
        e0 = fmaf(f4.x, c4, e0); e1 = fmaf(f4.y, c4, e1);
        e0 = fmaf(f5.x, c5, e0); e1 = fmaf(f5.y, c5, e1);
        e0 = fmaf(f6.x, c6, e0); e1 = fmaf(f6.y, c6, e1);
        e0 = fmaf(f7.x, c7, e0); e1 = fmaf(f7.y, c7, e1);

        g_enc[(size_t)(2 * l + 0) * N + idx] = e0;
        g_enc[(size_t)(2 * l + 1) * N + idx] = e1;
    }
}

// ================= K2: fused MLPs (FMA-bound, spill-free) =================
__global__ __launch_bounds__(128, 3)
void mlp_kernel(const float* __restrict__ dirp,
                const float* __restrict__ w1,
                const float* __restrict__ w2,
                const float* __restrict__ wr1,
                const float* __restrict__ wr2,
                const float* __restrict__ wr3,
                float* __restrict__ out, int N)
{
    __shared__ __align__(16) float sW1[32 * 64];
    __shared__ __align__(16) float sW2[64 * 20];   // 64x17 padded to stride 20
    __shared__ __align__(16) float sR1[32 * 64];
    __shared__ __align__(16) float sR2[64 * 64];
    __shared__ __align__(16) float sR3[64 * 4];    // 64x3 padded to stride 4

    const int tid = threadIdx.x;
    for (int i = tid; i < 32 * 64; i += 128) sW1[i] = w1[i];
    for (int i = tid; i < 64 * 20; i += 128) {
        int r = i / 20, c = i % 20;
        sW2[i] = (c < 17) ? w2[r * 17 + c] : 0.0f;
    }
    for (int i = tid; i < 32 * 64; i += 128) sR1[i] = wr1[i];
    for (int i = tid; i < 64 * 64; i += 128) sR2[i] = wr2[i];
    for (int i = tid; i < 64 * 4; i += 128) {
        int r = i / 4, c = i % 4;
        sR3[i] = (c < 3) ? wr3[r * 3 + c] : 0.0f;
    }
    __syncthreads();

    const int idx = blockIdx.x * 128 + tid;
    if (idx >= N) return;

    // ---------------- sigma layer 1: stream enc features, 64 accumulators ----------------
    float h[64];
    #pragma unroll
    for (int j = 0; j < 64; j++) h[j] = 0.0f;

    #pragma unroll
    for (int f = 0; f < 32; f++) {
        const float e = __ldg(&g_enc[(size_t)f * N + idx]);
        const float* wrow = sW1 + f * 64;
        #pragma unroll
        for (int j = 0; j < 64; j += 4) {
            const float4 wv = *(const float4*)(wrow + j);
            h[j + 0] = fmaf(e, wv.x, h[j + 0]);
            h[j + 1] = fmaf(e, wv.y, h[j + 1]);
            h[j + 2] = fmaf(e, wv.z, h[j + 2]);
            h[j + 3] = fmaf(e, wv.w, h[j + 3]);
        }
    }
    #pragma unroll
    for (int j = 0; j < 64; j++) h[j] = fmaxf(h[j], 0.0f);

    // ---------------- sigma layer 2: 64 -> 17 ----------------
    float g[20];
    #pragma unroll
    for (int j = 0; j < 20; j += 4) {
        float a0 = 0.f, a1 = 0.f, a2 = 0.f, a3 = 0.f;
        #pragma unroll
        for (int i = 0; i < 64; i++) {
            const float4 wv = *(const float4*)(sW2 + i * 20 + j);
            a0 = fmaf(h[i], wv.x, a0);
            a1 = fmaf(h[i], wv.y, a1);
            a2 = fmaf(h[i], wv.z, a2);
            a3 = fmaf(h[i], wv.w, a3);
        }
        g[j + 0] = a0; g[j + 1] = a1; g[j + 2] = a2; g[j + 3] = a3;
    }
    const float sigma = g[0];   // g[1..16] = geo_feat

    // ---------------- SH encode of direction ----------------
    const float dx = dirp[3 * idx + 0] * 2.0f - 1.0f;
    const float dy = dirp[3 * idx + 1] * 2.0f - 1.0f;
    const float dz = dirp[3 * idx + 2] * 2.0f - 1.0f;
    const float x2 = dx * dx, y2 = dy * dy, z2 = dz * dz;
    const float xy = dx * dy, yz = dy * dz, xz = dx * dz;

    float sh[16];
    sh[0]  = 0.28209479177387814f;
    sh[1]  = -0.48860251190291987f * dy;
    sh[2]  = 0.48860251190291987f * dz;
    sh[3]  = -0.48860251190291987f * dx;
    sh[4]  = 1.0925484305920792f * xy;
    sh[5]  = -1.0925484305920792f * yz;
    sh[6]  = 0.94617469575756f * z2 - 0.31539156525252f;
    sh[7]  = -1.0925484305920792f * xz;
    sh[8]  = 0.5462742152960396f * (x2 - y2);
    sh[9]  = 0.5900435899266435f * dy * (-3.0f * x2 + y2);
    sh[10] = 2.890611442640554f * xy * dz;
    sh[11] = 0.4570457994644657f * dy * (1.0f - 5.0f * z2);
    sh[12] = 0.3731763325901154f * dz * (5.0f * z2 - 3.0f);
    sh[13] = 0.4570457994644657f * dx * (1.0f - 5.0f * z2);
    sh[14] = 1.445305721320277f * dz * (x2 - y2);
    sh[15] = 0.5900435899266435f * dx * (-x2 + 3.0f * y2);

    // ---------------- rgb layer 1: 32 -> 64 (relu). h_old is dead; overwrite h ----------------
    // inputs: sh[0..15] then g[1..16]
    float hn[64];
    #pragma unroll
    for (int j = 0; j < 64; j += 4) {
        float a0 = 0.f, a1 = 0.f, a2 = 0.f, a3 = 0.f;
        #pragma unroll
        for (int i = 0; i < 16; i++) {
            const float4 wv = *(const float4*)(sR1 + i * 64 + j);
            a0 = fmaf(sh[i], wv.x, a0);
            a1 = fmaf(sh[i], wv.y, a1);
            a2 = fmaf(sh[i], wv.z, a2);
            a3 = fmaf(sh[i], wv.w, a3);
        }
        #pragma unroll
        for (int i = 0; i < 16; i++) {
            const float4 wv = *(const float4*)(sR1 + (16 + i) * 64 + j);
            a0 = fmaf(g[1 + i], wv.x, a0);
            a1 = fmaf(g[1 + i], wv.y, a1);
            a2 = fmaf(g[1 + i], wv.z, a2);
            a3 = fmaf(g[1 + i], wv.w, a3);
        }
        hn[j + 0] = fmaxf(a0, 0.f);
        hn[j + 1] = fmaxf(a1, 0.f);
        hn[j + 2] = fmaxf(a2, 0.f);
        hn[j + 3] = fmaxf(a3, 0.f);
    }

    // ---------------- rgb layers 2+3 fused: 64 -> relu -> 3 ----------------
    float r0 = 0.f, r1 = 0.f, r2 = 0.f;
    #pragma unroll
    for (int j = 0; j < 64; j += 2) {
        float a0 = 0.f, a1 = 0.f;
        #pragma unroll
        for (int i = 0; i < 64; i++) {
            const float2 wv = *(const float2*)(sR2 + i * 64 + j);
            a0 = fmaf(hn[i], wv.x, a0);
            a1 = fmaf(hn[i], wv.y, a1);
        }
        a0 = fmaxf(a0, 0.f);
        a1 = fmaxf(a1, 0.f);
        const float4 w3a = *(const float4*)(sR3 + (j + 0) * 4);
        const float4 w3b = *(const float4*)(sR3 + (j + 1) * 4);
        r0 = fmaf(a0, w3a.x, fmaf(a1, w3b.x, r0));
        r1 = fmaf(a0, w3a.y, fmaf(a1, w3b.y, r1));
        r2 = fmaf(a0, w3a.z, fmaf(a1, w3b.z, r2));
    }

    // ---------------- outputs: sigmoid(rgb) [N,3], relu(sigma) [N,1] ----------------
    out[3 * idx + 0] = 1.0f / (1.0f + __expf(-r0));
    out[3 * idx + 1] = 1.0f / (1.0f + __expf(-r1));
    out[3 * idx + 2] = 1.0f / (1.0f + __expf(-r2));
    out[(size_t)3 * N + idx] = fmaxf(sigma, 0.f);
}

extern "C" void kernel_launch(void* const* d_in, const int* in_sizes, int n_in,
                              void* d_out, int out_size)
{
    const float* xyz   = (const float*)d_in[0];
    const float* dirp  = (const float*)d_in[1];
    const float* table = (const float*)d_in[2];
    const float* w1    = (const float*)d_in[3];
    const float* w2    = (const float*)d_in[4];
    const float* wr1   = (const float*)d_in[5];
    const float* wr2   = (const float*)d_in[6];
    const float* wr3   = (const float*)d_in[7];
    float* out = (float*)d_out;

    const int N = in_sizes[0] / 3;
    encode_kernel<<<(N + 255) / 256, 256>>>(xyz, table, N);
    mlp_kernel<<<(N + 127) / 128, 128>>>(dirp, w1, w2, wr1, wr2, wr3, out, N);
}

// round 7
// speedup vs baseline: 1.9877x; 1.5130x over previous
#include <cuda_runtime.h>
#include <cuda_bf16.h>
#include <math.h>

#define NLEV 16
#define TBL (1u << 19)

// dynamic shared layout (floats)
#define OFF_W1 0            // 32*64   = 2048
#define OFF_W2 2048         // 64*20   = 1280 (17 padded to 20)
#define OFF_R1 3328         // 32*64   = 2048
#define OFF_R2 5376         // 64*64   = 4096
#define OFF_R3 9472         // 64*4    = 256  (3 padded to 4)
#define OFF_ACT 9728        // 128*65  = 8320
#define SMEM_FLOATS 18048   // 72192 bytes
#define ACT_STRIDE 65

// floor(16 * 1.3819^l) computed in double precision
__device__ __constant__ int c_res[16] = {16, 22, 30, 42, 58, 80, 111, 153,
                                         212, 294, 406, 561, 775, 1072, 1481, 2047};

__global__ __launch_bounds__(128)
void nerf_fused_kernel(const float* __restrict__ xyz,
                       const float* __restrict__ dirp,
                       const float* __restrict__ table,
                       const float* __restrict__ w1,
                       const float* __restrict__ w2,
                       const float* __restrict__ wr1,
                       const float* __restrict__ wr2,
                       const float* __restrict__ wr3,
                       float* __restrict__ out, int N)
{
    extern __shared__ __align__(16) float smem[];
    float* sW1 = smem + OFF_W1;
    float* sW2 = smem + OFF_W2;
    float* sR1 = smem + OFF_R1;
    float* sR2 = smem + OFF_R2;
    float* sR3 = smem + OFF_R3;

    const int tid = threadIdx.x;
    for (int i = tid; i < 32 * 64; i += 128) sW1[i] = w1[i];
    for (int i = tid; i < 64 * 20; i += 128) {
        int r = i / 20, c = i % 20;
        sW2[i] = (c < 17) ? w2[r * 17 + c] : 0.0f;
    }
    for (int i = tid; i < 32 * 64; i += 128) sR1[i] = wr1[i];
    for (int i = tid; i < 64 * 64; i += 128) sR2[i] = wr2[i];
    for (int i = tid; i < 64 * 4; i += 128) {
        int r = i / 4, c = i % 4;
        sR3[i] = (c < 3) ? wr3[r * 3 + c] : 0.0f;
    }
    __syncthreads();

    const int idx = blockIdx.x * 128 + tid;
    if (idx >= N) return;

    // each thread's private activation row in shared (conflict-free: stride 65)
    float* arow = smem + OFF_ACT + tid * ACT_STRIDE;

    const float x = xyz[3 * idx + 0];
    const float y = xyz[3 * idx + 1];
    const float z = xyz[3 * idx + 2];

    // ---------------- hash grid encode -> arow[0..31] ----------------
    #pragma unroll
    for (int l = 0; l < NLEV; l++) {
        const int res = c_res[l];
        const float rf = (float)res;
        const float px = x * rf, py = y * rf, pz = z * rf;
        const float fx = floorf(px), fy = floorf(py), fz = floorf(pz);
        const float wx = px - fx, wy = py - fy, wz = pz - fz;
        const unsigned X = (unsigned)fx, Y = (unsigned)fy, Z = (unsigned)fz;

        unsigned id0, id1, id2, id3, id4, id5, id6, id7;
        if (l < 5) {   // dense levels
            const unsigned s  = (unsigned)(res + 1);
            const unsigned s2 = s * s;
            const unsigned base = X + Y * s + Z * s2;
            id0 = base;          id1 = base + 1u;
            id2 = base + s;      id3 = base + s + 1u;
            id4 = base + s2;     id5 = base + s2 + 1u;
            id6 = base + s2 + s; id7 = base + s2 + s + 1u;
        } else {       // hashed levels
            const unsigned P1 = 2654435761u, P2 = 805459861u;
            const unsigned hx0 = X, hx1 = X + 1u;
            const unsigned hy0 = Y * P1, hy1 = (Y + 1u) * P1;
            const unsigned hz0 = Z * P2, hz1 = (Z + 1u) * P2;
            const unsigned M = TBL - 1u;
            id0 = (hx0 ^ hy0 ^ hz0) & M;  id1 = (hx1 ^ hy0 ^ hz0) & M;
            id2 = (hx0 ^ hy1 ^ hz0) & M;  id3 = (hx1 ^ hy1 ^ hz0) & M;
            id4 = (hx0 ^ hy0 ^ hz1) & M;  id5 = (hx1 ^ hy0 ^ hz1) & M;
            id6 = (hx0 ^ hy1 ^ hz1) & M;  id7 = (hx1 ^ hy1 ^ hz1) & M;
        }

        const float2* tl = (const float2*)table + (size_t)l * TBL;
        const float2 f0 = __ldg(tl + id0);
        const float2 f1 = __ldg(tl + id1);
        const float2 f2 = __ldg(tl + id2);
        const float2 f3 = __ldg(tl + id3);
        const float2 f4 = __ldg(tl + id4);
        const float2 f5 = __ldg(tl + id5);
        const float2 f6 = __ldg(tl + id6);
        const float2 f7 = __ldg(tl + id7);

        const float wx0 = 1.0f - wx, wy0 = 1.0f - wy, wz0 = 1.0f - wz;
        const float w00 = wy0 * wz0, w10 = wy * wz0, w01 = wy0 * wz, w11 = wy * wz;
        const float c0 = wx0 * w00, c1 = wx * w00;
        const float c2 = wx0 * w10, c3 = wx * w10;
        const float c4 = wx0 * w01, c5 = wx * w01;
        const float c6 = wx0 * w11, c7 = wx * w11;

        float e0 = f0.x * c0; float e1 = f0.y * c0;
        e0 = fmaf(f1.x, c1, e0); e1 = fmaf(f1.y, c1, e1);
        e0 = fmaf(f2.x, c2, e0); e1 = fmaf(f2.y, c2, e1);
        e0 = fmaf(f3.x, c3, e0); e1 = fmaf(f3.y, c3, e1);
        e0 = fmaf(f4.x, c4, e0); e1 = fmaf(f4.y, c4, e1);
        e0 = fmaf(f5.x, c5, e0); e1 = fmaf(f5.y, c5, e1);
        e0 = fmaf(f6.x, c6, e0); e1 = fmaf(f6.y, c6, e1);
        e0 = fmaf(f7.x, c7, e0); e1 = fmaf(f7.y, c7, e1);

        arow[2 * l + 0] = e0;
        arow[2 * l + 1] = e1;
    }

    // ---------------- sigma layer 1: 32 -> 64 relu (acc in regs, act in shared) ----------------
    {
        float acc[64];
        #pragma unroll
        for (int j = 0; j < 64; j++) acc[j] = 0.0f;
        #pragma unroll
        for (int k = 0; k < 32; k++) {
            const float e = arow[k];
            const float* wrow = sW1 + k * 64;
            #pragma unroll
            for (int j = 0; j < 64; j += 4) {
                const float4 wv = *(const float4*)(wrow + j);
                acc[j + 0] = fmaf(e, wv.x, acc[j + 0]);
                acc[j + 1] = fmaf(e, wv.y, acc[j + 1]);
                acc[j + 2] = fmaf(e, wv.z, acc[j + 2]);
                acc[j + 3] = fmaf(e, wv.w, acc[j + 3]);
            }
        }
        #pragma unroll
        for (int j = 0; j < 64; j++) arow[j] = fmaxf(acc[j], 0.0f);
    }

    // ---------------- sigma layer 2: 64 -> 17 (g in regs) ----------------
    float g[20];
    #pragma unroll
    for (int j = 0; j < 20; j += 4) {
        float a0 = 0.f, a1 = 0.f, a2 = 0.f, a3 = 0.f;
        #pragma unroll
        for (int i = 0; i < 64; i++) {
            const float e = arow[i];
            const float4 wv = *(const float4*)(sW2 + i * 20 + j);
            a0 = fmaf(e, wv.x, a0);
            a1 = fmaf(e, wv.y, a1);
            a2 = fmaf(e, wv.z, a2);
            a3 = fmaf(e, wv.w, a3);
        }
        g[j + 0] = a0; g[j + 1] = a1; g[j + 2] = a2; g[j + 3] = a3;
    }
    const float sigma = g[0];   // g[1..16] = geo_feat

    // ---------------- SH encode -> arow[0..15], geo_feat -> arow[16..31] ----------------
    {
        const float dx = dirp[3 * idx + 0] * 2.0f - 1.0f;
        const float dy = dirp[3 * idx + 1] * 2.0f - 1.0f;
        const float dz = dirp[3 * idx + 2] * 2.0f - 1.0f;
        const float x2 = dx * dx, y2 = dy * dy, z2 = dz * dz;
        const float xy = dx * dy, yz = dy * dz, xz = dx * dz;

        arow[0]  = 0.28209479177387814f;
        arow[1]  = -0.48860251190291987f * dy;
        arow[2]  = 0.48860251190291987f * dz;
        arow[3]  = -0.48860251190291987f * dx;
        arow[4]  = 1.0925484305920792f * xy;
        arow[5]  = -1.0925484305920792f * yz;
        arow[6]  = 0.94617469575756f * z2 - 0.31539156525252f;
        arow[7]  = -1.0925484305920792f * xz;
        arow[8]  = 0.5462742152960396f * (x2 - y2);
        arow[9]  = 0.5900435899266435f * dy * (-3.0f * x2 + y2);
        arow[10] = 2.890611442640554f * xy * dz;
        arow[11] = 0.4570457994644657f * dy * (1.0f - 5.0f * z2);
        arow[12] = 0.3731763325901154f * dz * (5.0f * z2 - 3.0f);
        arow[13] = 0.4570457994644657f * dx * (1.0f - 5.0f * z2);
        arow[14] = 1.445305721320277f * dz * (x2 - y2);
        arow[15] = 0.5900435899266435f * dx * (-x2 + 3.0f * y2);
        #pragma unroll
        for (int i = 0; i < 16; i++) arow[16 + i] = g[1 + i];
    }

    // ---------------- rgb layer 1: 32 -> 64 relu ----------------
    {
        float acc[64];
        #pragma unroll
        for (int j = 0; j < 64; j++) acc[j] = 0.0f;
        #pragma unroll
        for (int k = 0; k < 32; k++) {
            const float e = arow[k];
            const float* wrow = sR1 + k * 64;
            #pragma unroll
            for (int j = 0; j < 64; j += 4) {
                const float4 wv = *(const float4*)(wrow + j);
                acc[j + 0] = fmaf(e, wv.x, acc[j + 0]);
                acc[j + 1] = fmaf(e, wv.y, acc[j + 1]);
                acc[j + 2] = fmaf(e, wv.z, acc[j + 2]);
                acc[j + 3] = fmaf(e, wv.w, acc[j + 3]);
            }
        }
        #pragma unroll
        for (int j = 0; j < 64; j++) arow[j] = fmaxf(acc[j], 0.0f);
    }

    // ---------------- rgb layers 2+3 fused: 64 -> relu -> 3 ----------------
    float r0 = 0.f, r1 = 0.f, r2 = 0.f;
    #pragma unroll
    for (int j = 0; j < 64; j += 4) {
        float a0 = 0.f, a1 = 0.f, a2 = 0.f, a3 = 0.f;
        #pragma unroll
        for (int i = 0; i < 64; i++) {
            const float e = arow[i];
            const float4 wv = *(const float4*)(sR2 + i * 64 + j);
            a0 = fmaf(e, wv.x, a0);
            a1 = fmaf(e, wv.y, a1);
            a2 = fmaf(e, wv.z, a2);
            a3 = fmaf(e, wv.w, a3);
        }
        a0 = fmaxf(a0, 0.f);
        a1 = fmaxf(a1, 0.f);
        a2 = fmaxf(a2, 0.f);
        a3 = fmaxf(a3, 0.f);
        const float4 w3a = *(const float4*)(sR3 + (j + 0) * 4);
        const float4 w3b = *(const float4*)(sR3 + (j + 1) * 4);
        const float4 w3c = *(const float4*)(sR3 + (j + 2) * 4);
        const float4 w3d = *(const float4*)(sR3 + (j + 3) * 4);
        r0 = fmaf(a0, w3a.x, fmaf(a1, w3b.x, fmaf(a2, w3c.x, fmaf(a3, w3d.x, r0))));
        r1 = fmaf(a0, w3a.y, fmaf(a1, w3b.y, fmaf(a2, w3c.y, fmaf(a3, w3d.y, r1))));
        r2 = fmaf(a0, w3a.z, fmaf(a1, w3b.z, fmaf(a2, w3c.z, fmaf(a3, w3d.z, r2))));
    }

    // ---------------- outputs: sigmoid(rgb) [N,3], relu(sigma) [N,1] ----------------
    out[3 * idx + 0] = 1.0f / (1.0f + __expf(-r0));
    out[3 * idx + 1] = 1.0f / (1.0f + __expf(-r1));
    out[3 * idx + 2] = 1.0f / (1.0f + __expf(-r2));
    out[(size_t)3 * N + idx] = fmaxf(sigma, 0.f);
}

extern "C" void kernel_launch(void* const* d_in, const int* in_sizes, int n_in,
                              void* d_out, int out_size)
{
    const float* xyz   = (const float*)d_in[0];
    const float* dirp  = (const float*)d_in[1];
    const float* table = (const float*)d_in[2];
    const float* w1    = (const float*)d_in[3];
    const float* w2    = (const float*)d_in[4];
    const float* wr1   = (const float*)d_in[5];
    const float* wr2   = (const float*)d_in[6];
    const float* wr3   = (const float*)d_in[7];
    float* out = (float*)d_out;

    static int smem_set = 0;
    const int smem_bytes = SMEM_FLOATS * sizeof(float);
    if (!smem_set) {
        cudaFuncSetAttribute(nerf_fused_kernel,
                             cudaFuncAttributeMaxDynamicSharedMemorySize, smem_bytes);
        smem_set = 1;
    }

    const int N = in_sizes[0] / 3;
    const int grid = (N + 127) / 128;
    nerf_fused_kernel<<<grid, 128, smem_bytes>>>(xyz, dirp, table, w1, w2, wr1, wr2, wr3, out, N);
}

// round 8
// speedup vs baseline: 3.8883x; 1.9562x over previous
#include <cuda_runtime.h>
#include <cuda_bf16.h>
#include <math.h>

#define NLEV 16
#define TBL (1u << 19)

// ---- dynamic shared layout (float units) ----
// weights stored tf32-rounded; strides chosen so B-fragment loads are
// bank-conflict-free: stride % 32 == 8
#define OFF_W1 0            // [32][72]  = 2304
#define OFF_W2 2304         // [64][40]  = 2560  (N=17 padded to 24, zero-filled)
#define OFF_R1 4864         // [32][72]  = 2304
#define OFF_R2 7168         // [64][72]  = 4608
#define OFF_R3 11776        // [64][8]   = 512   (N=3 padded to 8, zero-filled)
#define OFF_ACT 12288       // 4 warps x [32][68] = 8704  (stride 68: A-frag loads conflict-free)
#define SMEM_FLOATS 20992   // 83968 bytes
#define ASTR 68

__device__ __constant__ int c_res[16] = {16, 22, 30, 42, 58, 80, 111, 153,
                                         212, 294, 406, 561, 775, 1072, 1481, 2047};

__device__ __forceinline__ float tf32r(float x) {
    unsigned u;
    asm("cvt.rna.tf32.f32 %0, %1;" : "=r"(u) : "f"(x));
    return __uint_as_float(u);
}

__device__ __forceinline__ void mma8(float* c, const unsigned* a, const unsigned* b) {
    asm volatile(
        "mma.sync.aligned.m16n8k8.row.col.f32.tf32.tf32.f32 "
        "{%0,%1,%2,%3}, {%4,%5,%6,%7}, {%8,%9}, {%0,%1,%2,%3};\n"
        : "+f"(c[0]), "+f"(c[1]), "+f"(c[2]), "+f"(c[3])
        : "r"(a[0]), "r"(a[1]), "r"(a[2]), "r"(a[3]), "r"(b[0]), "r"(b[1]));
}

__global__ __launch_bounds__(128)
void nerf_mma_kernel(const float* __restrict__ xyz,
                     const float* __restrict__ dirp,
                     const float* __restrict__ table,
                     const float* __restrict__ w1,
                     const float* __restrict__ w2,
                     const float* __restrict__ wr1,
                     const float* __restrict__ wr2,
                     const float* __restrict__ wr3,
                     float* __restrict__ out, int N)
{
    extern __shared__ __align__(16) float sm[];
    float* sW1 = sm + OFF_W1;
    float* sW2 = sm + OFF_W2;
    float* sR1 = sm + OFF_R1;
    float* sR2 = sm + OFF_R2;
    float* sR3 = sm + OFF_R3;

    const int tid = threadIdx.x;

    // -------- stage weights (tf32-rounded) --------
    for (int i = tid; i < 2560; i += 128) sW2[i] = 0.0f;
    for (int i = tid; i < 512;  i += 128) sR3[i] = 0.0f;
    __syncthreads();
    for (int i = tid; i < 32 * 64; i += 128) { int r = i >> 6, c = i & 63; sW1[r * 72 + c] = tf32r(w1[i]); }
    for (int i = tid; i < 64 * 17; i += 128) { int r = i / 17, c = i % 17; sW2[r * 40 + c] = tf32r(w2[i]); }
    for (int i = tid; i < 32 * 64; i += 128) { int r = i >> 6, c = i & 63; sR1[r * 72 + c] = tf32r(wr1[i]); }
    for (int i = tid; i < 64 * 64; i += 128) { int r = i >> 6, c = i & 63; sR2[r * 72 + c] = tf32r(wr2[i]); }
    for (int i = tid; i < 64 * 3;  i += 128) { int r = i / 3,  c = i % 3;  sR3[r * 8 + c]  = tf32r(wr3[i]); }
    __syncthreads();

    const int ln = tid & 31;
    const int wp = tid >> 5;
    const int g  = ln >> 2;      // group id (0..7)
    const int t  = ln & 3;       // thread-in-group (0..3)
    float* A = sm + OFF_ACT + wp * (32 * ASTR);

    const int base = blockIdx.x * 128 + wp * 32;   // first point of this warp's tile
    const int idx  = base + ln;
    const int pidx = idx < N ? idx : N - 1;
    const bool live = idx < N;

    // -------- direction load + SH basis (compute early, keep in regs) --------
    float sh[16];
    {
        const float dx = dirp[3 * pidx + 0] * 2.0f - 1.0f;
        const float dy = dirp[3 * pidx + 1] * 2.0f - 1.0f;
        const float dz = dirp[3 * pidx + 2] * 2.0f - 1.0f;
        const float x2 = dx * dx, y2 = dy * dy, z2 = dz * dz;
        const float xy = dx * dy, yz = dy * dz, xz = dx * dz;
        sh[0]  = 0.28209479177387814f;
        sh[1]  = -0.48860251190291987f * dy;
        sh[2]  = 0.48860251190291987f * dz;
        sh[3]  = -0.48860251190291987f * dx;
        sh[4]  = 1.0925484305920792f * xy;
        sh[5]  = -1.0925484305920792f * yz;
        sh[6]  = 0.94617469575756f * z2 - 0.31539156525252f;
        sh[7]  = -1.0925484305920792f * xz;
        sh[8]  = 0.5462742152960396f * (x2 - y2);
        sh[9]  = 0.5900435899266435f * dy * (-3.0f * x2 + y2);
        sh[10] = 2.890611442640554f * xy * dz;
        sh[11] = 0.4570457994644657f * dy * (1.0f - 5.0f * z2);
        sh[12] = 0.3731763325901154f * dz * (5.0f * z2 - 3.0f);
        sh[13] = 0.4570457994644657f * dx * (1.0f - 5.0f * z2);
        sh[14] = 1.445305721320277f * dz * (x2 - y2);
        sh[15] = 0.5900435899266435f * dx * (-x2 + 3.0f * y2);
    }

    // -------- hash-grid encode -> act row ln, cols 0..31 (tf32-rounded) --------
    {
        const float x = xyz[3 * pidx + 0];
        const float y = xyz[3 * pidx + 1];
        const float z = xyz[3 * pidx + 2];
        float* arow = A + ln * ASTR;

        #pragma unroll
        for (int l = 0; l < NLEV; l++) {
            const int res = c_res[l];
            const float rf = (float)res;
            const float px = x * rf, py = y * rf, pz = z * rf;
            const float fx = floorf(px), fy = floorf(py), fz = floorf(pz);
            const float wx = px - fx, wy = py - fy, wz = pz - fz;
            const unsigned X = (unsigned)fx, Y = (unsigned)fy, Z = (unsigned)fz;

            unsigned id0, id1, id2, id3, id4, id5, id6, id7;
            if (l < 5) {
                const unsigned s  = (unsigned)(res + 1);
                const unsigned s2 = s * s;
                const unsigned b0 = X + Y * s + Z * s2;
                id0 = b0;          id1 = b0 + 1u;
                id2 = b0 + s;      id3 = b0 + s + 1u;
                id4 = b0 + s2;     id5 = b0 + s2 + 1u;
                id6 = b0 + s2 + s; id7 = b0 + s2 + s + 1u;
            } else {
                const unsigned P1 = 2654435761u, P2 = 805459861u;
                const unsigned hx0 = X, hx1 = X + 1u;
                const unsigned hy0 = Y * P1, hy1 = (Y + 1u) * P1;
                const unsigned hz0 = Z * P2, hz1 = (Z + 1u) * P2;
                const unsigned M = TBL - 1u;
                id0 = (hx0 ^ hy0 ^ hz0) & M;  id1 = (hx1 ^ hy0 ^ hz0) & M;
                id2 = (hx0 ^ hy1 ^ hz0) & M;  id3 = (hx1 ^ hy1 ^ hz0) & M;
                id4 = (hx0 ^ hy0 ^ hz1) & M;  id5 = (hx1 ^ hy0 ^ hz1) & M;
                id6 = (hx0 ^ hy1 ^ hz1) & M;  id7 = (hx1 ^ hy1 ^ hz1) & M;
            }

            const float2* tl = (const float2*)table + (size_t)l * TBL;
            const float2 f0 = __ldg(tl + id0);
            const float2 f1 = __ldg(tl + id1);
            const float2 f2 = __ldg(tl + id2);
            const float2 f3 = __ldg(tl + id3);
            const float2 f4 = __ldg(tl + id4);
            const float2 f5 = __ldg(tl + id5);
            const float2 f6 = __ldg(tl + id6);
            const float2 f7 = __ldg(tl + id7);

            const float wx0 = 1.0f - wx, wy0 = 1.0f - wy, wz0 = 1.0f - wz;
            const float w00 = wy0 * wz0, w10 = wy * wz0, w01 = wy0 * wz, w11 = wy * wz;
            const float c0 = wx0 * w00, c1 = wx * w00;
            const float c2 = wx0 * w10, c3 = wx * w10;
            const float c4 = wx0 * w01, c5 = wx * w01;
            const float c6 = wx0 * w11, c7 = wx * w11;

            float e0 = f0.x * c0; float e1 = f0.y * c0;
            e0 = fmaf(f1.x, c1, e0); e1 = fmaf(f1.y, c1, e1);
            e0 = fmaf(f2.x, c2, e0); e1 = fmaf(f2.y, c2, e1);
            e0 = fmaf(f3.x, c3, e0); e1 = fmaf(f3.y, c3, e1);
            e0 = fmaf(f4.x, c4, e0); e1 = fmaf(f4.y, c4, e1);
            e0 = fmaf(f5.x, c5, e0); e1 = fmaf(f5.y, c5, e1);
            e0 = fmaf(f6.x, c6, e0); e1 = fmaf(f6.y, c6, e1);
            e0 = fmaf(f7.x, c7, e0); e1 = fmaf(f7.y, c7, e1);

            arow[2 * l + 0] = tf32r(e0);
            arow[2 * l + 1] = tf32r(e1);
        }
    }
    __syncwarp();

    // =============== sigma layer 1: [32x32] @ [32x64], relu ===============
    {
        unsigned a[2][4][4];
        #pragma unroll
        for (int mt = 0; mt < 2; mt++)
        #pragma unroll
        for (int kt = 0; kt < 4; kt++) {
            const int r = mt * 16 + g, k = kt * 8 + t;
            a[mt][kt][0] = __float_as_uint(A[(r    ) * ASTR + k    ]);
            a[mt][kt][1] = __float_as_uint(A[(r + 8) * ASTR + k    ]);
            a[mt][kt][2] = __float_as_uint(A[(r    ) * ASTR + k + 4]);
            a[mt][kt][3] = __float_as_uint(A[(r + 8) * ASTR + k + 4]);
        }
        __syncwarp();
        float acc[2][8][4];
        #pragma unroll
        for (int mt = 0; mt < 2; mt++)
        #pragma unroll
        for (int nt = 0; nt < 8; nt++)
        #pragma unroll
        for (int q = 0; q < 4; q++) acc[mt][nt][q] = 0.0f;

        #pragma unroll
        for (int nt = 0; nt < 8; nt++)
        #pragma unroll
        for (int kt = 0; kt < 4; kt++) {
            unsigned b[2];
            b[0] = __float_as_uint(sW1[(kt * 8 + t    ) * 72 + nt * 8 + g]);
            b[1] = __float_as_uint(sW1[(kt * 8 + t + 4) * 72 + nt * 8 + g]);
            mma8(acc[0][nt], a[0][kt], b);
            mma8(acc[1][nt], a[1][kt], b);
        }
        #pragma unroll
        for (int mt = 0; mt < 2; mt++)
        #pragma unroll
        for (int nt = 0; nt < 8; nt++) {
            const int r = mt * 16 + g, n = nt * 8 + 2 * t;
            A[(r    ) * ASTR + n    ] = tf32r(fmaxf(acc[mt][nt][0], 0.f));
            A[(r    ) * ASTR + n + 1] = tf32r(fmaxf(acc[mt][nt][1], 0.f));
            A[(r + 8) * ASTR + n    ] = tf32r(fmaxf(acc[mt][nt][2], 0.f));
            A[(r + 8) * ASTR + n + 1] = tf32r(fmaxf(acc[mt][nt][3], 0.f));
        }
    }
    __syncwarp();

    // =============== sigma layer 2: [32x64] @ [64x24], no activation ===============
    {
        unsigned a[2][8][4];
        #pragma unroll
        for (int mt = 0; mt < 2; mt++)
        #pragma unroll
        for (int kt = 0; kt < 8; kt++) {
            const int r = mt * 16 + g, k = kt * 8 + t;
            a[mt][kt][0] = __float_as_uint(A[(r    ) * ASTR + k    ]);
            a[mt][kt][1] = __float_as_uint(A[(r + 8) * ASTR + k    ]);
            a[mt][kt][2] = __float_as_uint(A[(r    ) * ASTR + k + 4]);
            a[mt][kt][3] = __float_as_uint(A[(r + 8) * ASTR + k + 4]);
        }
        __syncwarp();   // everyone finished reading h before we overwrite act

        float acc[2][3][4];
        #pragma unroll
        for (int mt = 0; mt < 2; mt++)
        #pragma unroll
        for (int nt = 0; nt < 3; nt++)
        #pragma unroll
        for (int q = 0; q < 4; q++) acc[mt][nt][q] = 0.0f;

        #pragma unroll
        for (int nt = 0; nt < 3; nt++)
        #pragma unroll
        for (int kt = 0; kt < 8; kt++) {
            unsigned b[2];
            b[0] = __float_as_uint(sW2[(kt * 8 + t    ) * 40 + nt * 8 + g]);
            b[1] = __float_as_uint(sW2[(kt * 8 + t + 4) * 40 + nt * 8 + g]);
            mma8(acc[0][nt], a[0][kt], b);
            mma8(acc[1][nt], a[1][kt], b);
        }

        // SH basis -> act cols 0..15 (own row)
        #pragma unroll
        for (int i = 0; i < 16; i++) A[ln * ASTR + i] = tf32r(sh[i]);

        // sigma (col 0) -> global; geometry cols 1..16 -> act cols 16..31
        #pragma unroll
        for (int mt = 0; mt < 2; mt++) {
            const int r = mt * 16 + g;
            #pragma unroll
            for (int nt = 0; nt < 3; nt++) {
                const int n0 = nt * 8 + 2 * t;
                const float v0 = acc[mt][nt][0], v1 = acc[mt][nt][1];
                const float v2 = acc[mt][nt][2], v3 = acc[mt][nt][3];
                if (n0 == 0) {
                    const int p0 = base + r, p1 = base + r + 8;
                    if (p0 < N) out[(size_t)3 * N + p0] = fmaxf(v0, 0.f);
                    if (p1 < N) out[(size_t)3 * N + p1] = fmaxf(v2, 0.f);
                } else if (n0 >= 1 && n0 <= 16) {
                    A[(r    ) * ASTR + 15 + n0] = tf32r(v0);
                    A[(r + 8) * ASTR + 15 + n0] = tf32r(v2);
                }
                const int n1 = n0 + 1;
                if (n1 >= 1 && n1 <= 16) {
                    A[(r    ) * ASTR + 15 + n1] = tf32r(v1);
                    A[(r + 8) * ASTR + 15 + n1] = tf32r(v3);
                }
            }
        }
    }
    __syncwarp();

    // =============== rgb layer 1: [32x32] @ [32x64], relu ===============
    {
        unsigned a[2][4][4];
        #pragma unroll
        for (int mt = 0; mt < 2; mt++)
        #pragma unroll
        for (int kt = 0; kt < 4; kt++) {
            const int r = mt * 16 + g, k = kt * 8 + t;
            a[mt][kt][0] = __float_as_uint(A[(r    ) * ASTR + k    ]);
            a[mt][kt][1] = __float_as_uint(A[(r + 8) * ASTR + k    ]);
            a[mt][kt][2] = __float_as_uint(A[(r    ) * ASTR + k + 4]);
            a[mt][kt][3] = __float_as_uint(A[(r + 8) * ASTR + k + 4]);
        }
        __syncwarp();
        float acc[2][8][4];
        #pragma unroll
        for (int mt = 0; mt < 2; mt++)
        #pragma unroll
        for (int nt = 0; nt < 8; nt++)
        #pragma unroll
        for (int q = 0; q < 4; q++) acc[mt][nt][q] = 0.0f;

        #pragma unroll
        for (int nt = 0; nt < 8; nt++)
        #pragma unroll
        for (int kt = 0; kt < 4; kt++) {
            unsigned b[2];
            b[0] = __float_as_uint(sR1[(kt * 8 + t    ) * 72 + nt * 8 + g]);
            b[1] = __float_as_uint(sR1[(kt * 8 + t + 4) * 72 + nt * 8 + g]);
            mma8(acc[0][nt], a[0][kt], b);
            mma8(acc[1][nt], a[1][kt], b);
        }
        #pragma unroll
        for (int mt = 0; mt < 2; mt++)
        #pragma unroll
        for (int nt = 0; nt < 8; nt++) {
            const int r = mt * 16 + g, n = nt * 8 + 2 * t;
            A[(r    ) * ASTR + n    ] = tf32r(fmaxf(acc[mt][nt][0], 0.f));
            A[(r    ) * ASTR + n + 1] = tf32r(fmaxf(acc[mt][nt][1], 0.f));
            A[(r + 8) * ASTR + n    ] = tf32r(fmaxf(acc[mt][nt][2], 0.f));
            A[(r + 8) * ASTR + n + 1] = tf32r(fmaxf(acc[mt][nt][3], 0.f));
        }
    }
    __syncwarp();

    // =============== rgb layer 2: [32x64] @ [64x64], relu ===============
    {
        unsigned a[2][8][4];
        #pragma unroll
        for (int mt = 0; mt < 2; mt++)
        #pragma unroll
        for (int kt = 0; kt < 8; kt++) {
            const int r = mt * 16 + g, k = kt * 8 + t;
            a[mt][kt][0] = __float_as_uint(A[(r    ) * ASTR + k    ]);
            a[mt][kt][1] = __float_as_uint(A[(r + 8) * ASTR + k    ]);
            a[mt][kt][2] = __float_as_uint(A[(r    ) * ASTR + k + 4]);
            a[mt][kt][3] = __float_as_uint(A[(r + 8) * ASTR + k + 4]);
        }
        __syncwarp();
        float acc[2][8][4];
        #pragma unroll
        for (int mt = 0; mt < 2; mt++)
        #pragma unroll
        for (int nt = 0; nt < 8; nt++)
        #pragma unroll
        for (int q = 0; q < 4; q++) acc[mt][nt][q] = 0.0f;

        #pragma unroll
        for (int nt = 0; nt < 8; nt++)
        #pragma unroll
        for (int kt = 0; kt < 8; kt++) {
            unsigned b[2];
            b[0] = __float_as_uint(sR2[(kt * 8 + t    ) * 72 + nt * 8 + g]);
            b[1] = __float_as_uint(sR2[(kt * 8 + t + 4) * 72 + nt * 8 + g]);
            mma8(acc[0][nt], a[0][kt], b);
            mma8(acc[1][nt], a[1][kt], b);
        }
        #pragma unroll
        for (int mt = 0; mt < 2; mt++)
        #pragma unroll
        for (int nt = 0; nt < 8; nt++) {
            const int r = mt * 16 + g, n = nt * 8 + 2 * t;
            A[(r    ) * ASTR + n    ] = tf32r(fmaxf(acc[mt][nt][0], 0.f));
            A[(r    ) * ASTR + n + 1] = tf32r(fmaxf(acc[mt][nt][1], 0.f));
            A[(r + 8) * ASTR + n    ] = tf32r(fmaxf(acc[mt][nt][2], 0.f));
            A[(r + 8) * ASTR + n + 1] = tf32r(fmaxf(acc[mt][nt][3], 0.f));
        }
    }
    __syncwarp();

    // =============== rgb layer 3: [32x64] @ [64x8] (cols 0..2 real), sigmoid ===============
    {
        unsigned a[2][8][4];
        #pragma unroll
        for (int mt = 0; mt < 2; mt++)
        #pragma unroll
        for (int kt = 0; kt < 8; kt++) {
            const int r = mt * 16 + g, k = kt * 8 + t;
            a[mt][kt][0] = __float_as_uint(A[(r    ) * ASTR + k    ]);
            a[mt][kt][1] = __float_as_uint(A[(r + 8) * ASTR + k    ]);
            a[mt][kt][2] = __float_as_uint(A[(r    ) * ASTR + k + 4]);
            a[mt][kt][3] = __float_as_uint(A[(r + 8) * ASTR + k + 4]);
        }
        float acc[2][4];
        #pragma unroll
        for (int mt = 0; mt < 2; mt++)
        #pragma unroll
        for (int q = 0; q < 4; q++) acc[mt][q] = 0.0f;

        #pragma unroll
        for (int kt = 0; kt < 8; kt++) {
            unsigned b[2];
            b[0] = __float_as_uint(sR3[(kt * 8 + t    ) * 8 + g]);
            b[1] = __float_as_uint(sR3[(kt * 8 + t + 4) * 8 + g]);
            mma8(acc[0], a[0][kt], b);
            mma8(acc[1], a[1][kt], b);
        }
        const int n0 = 2 * t;
        #pragma unroll
        for (int mt = 0; mt < 2; mt++) {
            const int r = mt * 16 + g;
            const int p0 = base + r, p1 = base + r + 8;
            if (n0 < 3) {
                if (p0 < N) out[3 * p0 + n0] = 1.0f / (1.0f + __expf(-acc[mt][0]));
                if (p1 < N) out[3 * p1 + n0] = 1.0f / (1.0f + __expf(-acc[mt][2]));
            }
            if (n0 + 1 < 3) {
                if (p0 < N) out[3 * p0 + n0 + 1] = 1.0f / (1.0f + __expf(-acc[mt][1]));
                if (p1 < N) out[3 * p1 + n0 + 1] = 1.0f / (1.0f + __expf(-acc[mt][3]));
            }
        }
    }
    (void)live;
}

extern "C" void kernel_launch(void* const* d_in, const int* in_sizes, int n_in,
                              void* d_out, int out_size)
{
    const float* xyz   = (const float*)d_in[0];
    const float* dirp  = (const float*)d_in[1];
    const float* table = (const float*)d_in[2];
    const float* w1    = (const float*)d_in[3];
    const float* w2    = (const float*)d_in[4];
    const float* wr1   = (const float*)d_in[5];
    const float* wr2   = (const float*)d_in[6];
    const float* wr3   = (const float*)d_in[7];
    float* out = (float*)d_out;

    static int smem_set = 0;
    const int smem_bytes = SMEM_FLOATS * sizeof(float);
    if (!smem_set) {
        cudaFuncSetAttribute(nerf_mma_kernel,
                             cudaFuncAttributeMaxDynamicSharedMemorySize, smem_bytes);
        smem_set = 1;
    }

    const int N = in_sizes[0] / 3;
    const int grid = (N + 127) / 128;
    nerf_mma_kernel<<<grid, 128, smem_bytes>>>(xyz, dirp, table, w1, w2, wr1, wr2, wr3, out, N);
}